// round 7
// baseline (speedup 1.0000x reference)
#include <cuda_runtime.h>
#include <cuda_bf16.h>
#include <math_constants.h>

#define LOOK_LONG  63
#define NFEAT      16
#define ROW_STRIDE (LOOK_LONG * NFEAT)   // 1008 floats per batch row
#define NOUT       21
#define ROWS_PER_WARP 2                  // 16 lanes per row
#define WARPS_PER_BLOCK 4
#define THREADS    (WARPS_PER_BLOCK * 32)
#define ROWS_PER_BLOCK (WARPS_PER_BLOCK * ROWS_PER_WARP)   // 8
#define SSTRIDE    80                    // smem floats per row (conflict-free padding)

__device__ __forceinline__ float grp_sum(float v) {
    v += __shfl_xor_sync(0xffffffffu, v, 8);
    v += __shfl_xor_sync(0xffffffffu, v, 4);
    v += __shfl_xor_sync(0xffffffffu, v, 2);
    v += __shfl_xor_sync(0xffffffffu, v, 1);
    return v;
}
__device__ __forceinline__ float grp_max(float v) {
    v = fmaxf(v, __shfl_xor_sync(0xffffffffu, v, 8));
    v = fmaxf(v, __shfl_xor_sync(0xffffffffu, v, 4));
    v = fmaxf(v, __shfl_xor_sync(0xffffffffu, v, 2));
    v = fmaxf(v, __shfl_xor_sync(0xffffffffu, v, 1));
    return v;
}
__device__ __forceinline__ float grp_min(float v) {
    v = fminf(v, __shfl_xor_sync(0xffffffffu, v, 8));
    v = fminf(v, __shfl_xor_sync(0xffffffffu, v, 4));
    v = fminf(v, __shfl_xor_sync(0xffffffffu, v, 2));
    v = fminf(v, __shfl_xor_sync(0xffffffffu, v, 1));
    return v;
}

__global__ __launch_bounds__(THREADS)
void regime_feature_kernel(const float* __restrict__ x,
                           float* __restrict__ out,
                           int B) {
    const int lane = threadIdx.x & 31;
    const int wrp  = threadIdx.x >> 5;
    const int h    = lane >> 4;          // sub-row 0..1
    const int i    = lane & 15;          // lane within sub-row
    const int row  = blockIdx.x * ROWS_PER_BLOCK + wrp * ROWS_PER_WARP + h;
    const int row_c = (row < B) ? row : (B - 1);

    __shared__ float s_r[WARPS_PER_BLOCK][ROWS_PER_WARP * SSTRIDE];
    float* sr = s_r[wrp] + h * SSTRIDE;

    const float* __restrict__ xr = x + (size_t)row_c * ROW_STRIDE;

    // ---- front-batched streaming loads: 4 r values (t = i + 16k), vf, rsi, mom ----
    float xv[4];
#pragma unroll
    for (int k = 0; k < 4; ++k) {
        const int t = i + 16 * k;
        if (k < 3) xv[k] = __ldcs(xr + t * NFEAT);
        else       xv[k] = (i < 15) ? __ldcs(xr + t * NFEAT) : 0.0f;  // t=63 -> 0
    }
    float vfacc = __ldcs(xr + (42 + i) * NFEAT + 10);   // t = 42..57
    if (i < 5) vfacc += __ldcs(xr + (58 + i) * NFEAT + 10);  // t = 58..62
    const float rsi  = __ldcs(xr + 62 * NFEAT + 1);
    const float momc = __ldcs(xr + 62 * NFEAT + 15);

    // ---- stage r into smem (slot 63 gets 0 from lane i==15) ----
#pragma unroll
    for (int k = 0; k < 4; ++k) sr[i + 16 * k] = xv[k];
    __syncwarp();

    // ---- serial pass over 4 owned values ----
    float sum = 0.f, ssq = 0.f, sr3 = 0.f, sab = 0.f, shs = 0.f, shq = 0.f;
    float mx = -CUDART_INF_F, mn = CUDART_INF_F;
#pragma unroll
    for (int k = 0; k < 4; ++k) {
        const float xx = xv[k];
        const float x2 = xx * xx;
        sum += xx;
        ssq += x2;
        sr3 = fmaf(x2, xx, sr3);
        sab += fabsf(xx);
        // short window t in [42,62]: k==2 if i>=10 (t=42..47); k==3 always (t=48..62, xv=0 for i=15)
        if (k == 2) { const bool p = (i >= 10); shs += p ? xx : 0.f; shq += p ? x2 : 0.f; }
        if (k == 3) { shs += xx; shq += x2; }
        if (k == 3) { const bool v3 = (i < 15);
                      mx = v3 ? fmaxf(mx, xx) : mx;
                      mn = v3 ? fminf(mn, xx) : mn; }
        else        { mx = fmaxf(mx, xx); mn = fminf(mn, xx); }
    }

    // ---- lag-1 products: r[t]*r[t+1], t=0..61; t=62 hits sr[63]=0 ----
    float abacc = 0.f;
#pragma unroll
    for (int k = 0; k < 4; ++k) {
        int idx = i + 16 * k + 1;
        if (k == 3) idx = (idx > 63) ? 63 : idx;    // i=15: xv=0 anyway
        abacc = fmaf(xv[k], sr[idx], abacc);
    }

    // ---- 4-step subgroup reductions (each serves 2 rows) ----
    sum   = grp_sum(sum);
    ssq   = grp_sum(ssq);
    sr3   = grp_sum(sr3);
    sab   = grp_sum(sab);
    shs   = grp_sum(shs);
    shq   = grp_sum(shq);
    abacc = grp_sum(abacc);
    vfacc = grp_sum(vfacc);
    mx    = grp_max(mx);
    mn    = grp_min(mn);

    // ---- sliding-window stds: all 9 windows in one pass (lanes 0..8) ----
    float vs_i = 0.f;
    {
        const int wbase = 41 - 5 * ((i < 9) ? i : 8);   // window i: r[41-5i .. 62-5i]
        float ws = 0.f, wq = 0.f;
#pragma unroll
        for (int k = 0; k < 22; ++k) {
            const float v = sr[wbase + k];
            ws += v;
            wq = fmaf(v, v, wq);
        }
        vs_i = sqrtf(fmaxf(0.f, (wq - ws * ws * (1.0f / 22.0f))) * (1.0f / 21.0f));
    }
    const float vs_m = (i < 9) ? vs_i : 0.f;
    const float vs_sum  = grp_sum(vs_m);
    const float vs_sum2 = grp_sum(vs_m * vs_m);
    const float m_vs = vs_sum * (1.0f / 9.0f);
    const float vol_persistence = sqrtf(fmaxf(0.f, vs_sum2 * (1.0f / 9.0f) - m_vs * m_vs));
    const int gbase = lane & ~15;
    const float vs0 = __shfl_sync(0xffffffffu, vs_i, gbase);
    const float vs8 = __shfl_sync(0xffffffffu, vs_i, gbase + 8);
    const float vol_trend = vs0 - vs8;

    // ---- derived scalars (uniform within each 16-lane subgroup) ----
    const float n = 63.0f;
    const float mean = sum / n;
    const float var_long = fmaxf(0.f, (ssq - sum * sum / n)) * (1.0f / 62.0f);
    const float vol_long = sqrtf(var_long);
    const float var_s = fmaxf(0.f, (shq - shs * shs * (1.0f / 21.0f))) * (1.0f / 20.0f);
    const float vol_short = sqrtf(var_s);
    const float vol_ratio = vol_short / (vol_long + 1e-8f);
    const float high_vol = (vol_short > 0.03f) ? 1.0f : 0.0f;
    const float med_vol  = ((vol_short >= 0.01f) && (vol_short <= 0.03f)) ? 1.0f : 0.0f;
    const float low_vol  = (vol_short < 0.01f) ? 1.0f : 0.0f;

    const float rfirst = sr[0], rlast = sr[62], r42 = sr[42];
    const float sa  = sum - rlast;
    const float sb  = sum - rfirst;
    const float saa = ssq - rlast * rlast;
    const float sbb = ssq - rfirst * rfirst;
    const float cnum = abacc - sa * sb * (1.0f / 62.0f);
    const float cden = sqrtf((saa - sa * sa * (1.0f / 62.0f)) * (sbb - sb * sb * (1.0f / 62.0f)));
    const float corr = cnum / cden;
    const float trend_strength = (corr != corr) ? 0.5f : fabsf(corr);

    float skewness = 0.0f;
    if (vol_long >= 1e-8f) {
        const float c3 = sr3 - 3.0f * mean * ssq + 2.0f * mean * mean * sum;
        skewness = (c3 / n) / (vol_long * vol_long * vol_long);
    }

    const float momentum_short = rlast / (r42 + 1e-8f) - 1.0f;
    const float return_range = mx - mn;
    const float vol_feature_mean = vfacc * (1.0f / 21.0f);
    const float abs_mean = sab / n;

    // ---- each lane writes feature i; lanes 0..4 also write i+16 ----
    float a0, a2 = 0.0f;
    switch (i) {
        case 0:  a0 = high_vol;        a2 = 0.0f;            break; // f16 rel_strength
        case 1:  a0 = med_vol;         a2 = 0.02f;           break; // f17 mkt_vol
        case 2:  a0 = low_vol;         a2 = vol_persistence; break; // f18
        case 3:  a0 = trend_strength;  a2 = vol_trend;       break; // f19
        case 4:  a0 = vol_ratio;       a2 = 0.0f;            break; // f20 regime_shift
        case 5:  a0 = mean;            break;
        case 6:  a0 = abs_mean;        break;
        case 7:  a0 = return_range;    break;
        case 8:  a0 = skewness;        break;
        case 9:  a0 = momentum_short;  break;
        case 10: a0 = rsi;             break;
        case 11: a0 = vol_feature_mean;break;
        case 12: a0 = momc;            break;
        case 13: a0 = 0.0f;            break; // relative_return
        case 14: a0 = 1.0f;            break; // relative_vol
        default: a0 = 1.0f;            break; // beta (i==15)
    }
    if (row < B) {
        float* o = out + (size_t)row * NOUT;
        o[i] = a0;
        if (i < 5) o[i + 16] = a2;
    }
}

extern "C" void kernel_launch(void* const* d_in, const int* in_sizes, int n_in,
                              void* d_out, int out_size) {
    const float* x = (const float*)d_in[0];
    float* out = (float*)d_out;
    int B = in_sizes[0] / ROW_STRIDE;
    int blocks = (B + ROWS_PER_BLOCK - 1) / ROWS_PER_BLOCK;
    regime_feature_kernel<<<blocks, THREADS>>>(x, out, B);
}